// round 16
// baseline (speedup 1.0000x reference)
#include <cuda_runtime.h>
#include <math.h>

#define Bn 16
#define Cn 64
#define Hn 256
#define Wn 256
#define M0 20
#define M1 20

typedef unsigned long long ull;

// ---- packed f32x2 helpers (Blackwell FFMA2 path, PTX-only) ----
__device__ __forceinline__ ull pk2(float lo, float hi) {
    ull r; asm("mov.b64 %0, {%1,%2};" : "=l"(r) : "f"(lo), "f"(hi)); return r;
}
__device__ __forceinline__ ull bc2(float v) {
    ull r; asm("mov.b64 %0, {%1,%1};" : "=l"(r) : "f"(v)); return r;
}
__device__ __forceinline__ ull ffma2(ull a, ull b, ull c) {
    ull d; asm("fma.rn.f32x2 %0, %1, %2, %3;" : "=l"(d) : "l"(a), "l"(b), "l"(c)); return d;
}
__device__ __forceinline__ ull fmul2(ull a, ull b) {
    ull d; asm("mul.rn.f32x2 %0, %1, %2;" : "=l"(d) : "l"(a), "l"(b)); return d;
}
__device__ __forceinline__ void upk2(ull v, float& lo, float& hi) {
    asm("mov.b64 {%0,%1}, %2;" : "=f"(lo), "=f"(hi) : "l"(v));
}

// Scratch (device globals; allocation-free per harness rules)
__device__ float2 g_tw[256];                 // e^{+2*pi*i*m/256}
__device__ float2 g_T1[Bn*Cn*M1*Hn];         // [b*64+i][kx][y]
__device__ float2 g_Xf[Bn*M0*M1*Cn];         // [b][ky][kx][i]
__device__ float2 g_Yf[Bn*M0*M1*Cn];         // [b][ky][kx][o]
__device__ float2 g_T2[Bn*Cn*Hn*M1];         // [b*64+o][y][kx]
__device__ float2 g_Wt[M0*M1*Cn*Cn];         // [mode][i*64+o]  pre-transposed weights

__global__ void k_init() {
    int m = threadIdx.x;
    double s, c;
    sincospi((double)m / 128.0, &s, &c);
    g_tw[m] = make_float2((float)c, (float)s);
}

// ---------------- weight transpose for k_mix ----------------
__global__ __launch_bounds__(256) void k_wt(const float* __restrict__ wr, const float* __restrict__ wi) {
    __shared__ float2 ts[64][51];
    int tid = threadIdx.x;
    int io0 = (blockIdx.x & 63) * 64;
    int m0  = (blockIdx.x >> 6) * 50;
    for (int idx = tid; idx < 64 * 50; idx += 256) {
        int r = idx / 50, c = idx - r * 50;
        int g = (io0 + r) * 400 + (m0 + c);
        ts[r][c] = make_float2(wr[g], wi[g]);
    }
    __syncthreads();
    for (int idx = tid; idx < 64 * 50; idx += 256) {
        int mc = idx >> 6, rc = idx & 63;
        g_Wt[(size_t)(m0 + mc) * 4096 + io0 + rc] = ts[rc][mc];
    }
}

// ---------------- Kernel 1: forward DFT along x (FFMA2, conflict-free) ----------------
__global__ __launch_bounds__(256) void k_fwdx(const float* __restrict__ x) {
    __shared__ float As[32][258];
    __shared__ float Bs[32][40];
    __shared__ float2 tws[256];
    int tid = threadIdx.x;
    tws[tid] = g_tw[tid];
    int rowBase = blockIdx.x * 256;
    int rowg = tid & 31, colg = tid >> 5;

    ull acc[4][5];
#pragma unroll
    for (int r = 0; r < 4; r++)
#pragma unroll
        for (int j = 0; j < 5; j++) acc[r][j] = 0ull;

    for (int kc = 0; kc < 256; kc += 32) {
        __syncthreads();
#pragma unroll
        for (int e = 0; e < 32; e++) {
            int idx = tid + 256 * e;
            int kloc = idx & 31;
            int r = idx >> 5;
            As[kloc][r] = x[(size_t)(rowBase + r) * 256 + kc + kloc];
        }
#pragma unroll
        for (int e = 0; e < 5; e++) {
            int idx = tid + 256 * e;
            int kloc = idx / 40;
            int j = idx - kloc * 40;
            int kx = j >> 1;
            float2 t = tws[(kx * (kc + kloc)) & 255];
            Bs[kloc][j] = (j & 1) ? -t.y : t.x;
        }
        __syncthreads();
#pragma unroll
        for (int k = 0; k < 32; k++) {
            const ull* Abase = (const ull*)(&As[k][0]);
            ull a0 = Abase[rowg];
            ull a1 = Abase[rowg + 32];
            ull a2 = Abase[rowg + 64];
            ull a3 = Abase[rowg + 96];
            ull bv[5];
#pragma unroll
            for (int j = 0; j < 5; j++) bv[j] = bc2(Bs[k][colg * 5 + j]);
#pragma unroll
            for (int j = 0; j < 5; j++) {
                acc[0][j] = ffma2(a0, bv[j], acc[0][j]);
                acc[1][j] = ffma2(a1, bv[j], acc[1][j]);
                acc[2][j] = ffma2(a2, bv[j], acc[2][j]);
                acc[3][j] = ffma2(a3, bv[j], acc[3][j]);
            }
        }
    }
    float* T1f = (float*)g_T1;
#pragma unroll
    for (int rp = 0; rp < 4; rp++) {
#pragma unroll
        for (int j = 0; j < 5; j++) {
            float lo, hi;
            upk2(acc[rp][j], lo, hi);
            int jj = colg * 5 + j;
            int kx = jj >> 1, part = jj & 1;
            int row0 = rowBase + 2 * rowg + 64 * rp;
            int bi0 = row0 >> 8, y0 = row0 & 255;
            int row1 = row0 + 1;
            int bi1 = row1 >> 8, y1 = row1 & 255;
            T1f[(((size_t)bi0 * M1 + kx) * Hn + y0) * 2 + part] = lo;
            T1f[(((size_t)bi1 * M1 + kx) * Hn + y1) * 2 + part] = hi;
        }
    }
}

// ---------------- Kernel 2: forward DFT along y (4 channels/block, packed re/im) ----------------
// thread t<200: (ky pair, kx); 4 i-channels; acc = (re,im) via (vx,vy)(c,c) + (vy,-vx)(s,s)
#define T1PITCH 5140   // 20 * 257
__global__ __launch_bounds__(256) void k_fwdy() {
    extern __shared__ char dsm[];
    float2* T1s = (float2*)dsm;                    // [4][20][257]
    ull* twc = (ull*)(dsm + 4 * T1PITCH * 8);      // (c,c) x256
    ull* twn = twc + 256;                          // (s,s) x256
    int tid = threadIdx.x;
    {
        float2 t = g_tw[tid];
        twc[tid] = bc2(t.x);
        twn[tid] = bc2(t.y);
    }
    int bi0 = blockIdx.x * 4;
    const float2* src = g_T1 + (size_t)bi0 * (M1 * Hn);
    for (int idx = tid; idx < 4 * M1 * Hn; idx += 256) {
        int iloc = idx / 5120;
        int rem = idx - iloc * 5120;
        int kx = rem >> 8, y = rem & 255;
        T1s[iloc * T1PITCH + kx * 257 + y] = src[idx];
    }
    __syncthreads();

    if (tid < 200) {
        int kyp = tid / 20, kx = tid - kyp * 20;
        int ky0 = 2 * kyp;
        ull a[4][2];
#pragma unroll
        for (int i = 0; i < 4; i++) { a[i][0] = 0ull; a[i][1] = 0ull; }
        const ull* v0 = (const ull*)(T1s + 0 * T1PITCH + kx * 257);
        const ull* v1 = (const ull*)(T1s + 1 * T1PITCH + kx * 257);
        const ull* v2 = (const ull*)(T1s + 2 * T1PITCH + kx * 257);
        const ull* v3 = (const ull*)(T1s + 3 * T1PITCH + kx * 257);
#pragma unroll 4
        for (int y = 0; y < Hn; y++) {
            int i0 = (ky0 * y) & 255;
            int i1 = ((ky0 + 1) * y) & 255;
            ull c0 = twc[i0], n0 = twn[i0];
            ull c1 = twc[i1], n1 = twn[i1];
            ull v[4] = {v0[y], v1[y], v2[y], v3[y]};
#pragma unroll
            for (int i = 0; i < 4; i++) {
                float vx, vy;
                upk2(v[i], vx, vy);
                ull vs = pk2(vy, -vx);
                a[i][0] = ffma2(v[i], c0, a[i][0]);
                a[i][0] = ffma2(vs, n0, a[i][0]);
                a[i][1] = ffma2(v[i], c1, a[i][1]);
                a[i][1] = ffma2(vs, n1, a[i][1]);
            }
        }
        int b = bi0 >> 6, ib = bi0 & 63;
#pragma unroll
        for (int i = 0; i < 4; i++) {
#pragma unroll
            for (int j = 0; j < 2; j++) {
                float re, im;
                upk2(a[i][j], re, im);
                g_Xf[((size_t)(b * M0 + ky0 + j) * M1 + kx) * Cn + ib + i] = make_float2(re, im);
            }
        }
    }
}

// ---------------- Kernel 3: mixing (512 threads, packed complex FFMA2) ----------------
__global__ __launch_bounds__(512) void k_mix() {
    __shared__ ull Ws[Cn * Cn];      // (wr,wi)
    __shared__ ull Wsw[Cn * Cn];     // (wi,wr)
    __shared__ ull Xa[Bn * Cn];      // (xr,xr)
    __shared__ ull Xb[Bn * Cn];      // (-xi,xi)
    int tid = threadIdx.x;
    int mode = blockIdx.x;
    const float2* wsrc = g_Wt + (size_t)mode * 4096;
    for (int idx = tid; idx < Cn * Cn; idx += 512) {
        float2 w = wsrc[idx];
        Ws[idx]  = pk2(w.x, w.y);
        Wsw[idx] = pk2(w.y, w.x);
    }
    for (int idx = tid; idx < Bn * Cn; idx += 512) {
        int b = idx >> 6, i = idx & 63;
        float2 xv = g_Xf[((size_t)b * 400 + mode) * Cn + i];
        Xa[idx] = bc2(xv.x);
        Xb[idx] = pk2(-xv.y, xv.y);
    }
    __syncthreads();
    const float SC = 1.0f / 65536.0f;
    int o = tid & 63, bh = tid >> 6;          // bh 0..7 -> b = bh, bh+8
    ull r0 = 0ull, r1 = 0ull;
#pragma unroll 8
    for (int i = 0; i < Cn; i++) {
        ull w = Ws[i * 64 + o];
        ull wsw = Wsw[i * 64 + o];
        r0 = ffma2(Xa[bh * 64 + i], w, r0);
        r0 = ffma2(Xb[bh * 64 + i], wsw, r0);
        r1 = ffma2(Xa[(bh + 8) * 64 + i], w, r1);
        r1 = ffma2(Xb[(bh + 8) * 64 + i], wsw, r1);
    }
    float re, im;
    upk2(r0, re, im);
    g_Yf[((size_t)bh * 400 + mode) * Cn + o] = make_float2(re * SC, im * SC);
    upk2(r1, re, im);
    g_Yf[((size_t)(bh + 8) * 400 + mode) * Cn + o] = make_float2(re * SC, im * SC);
}

// ---------------- Kernel 4: inverse DFT along y ----------------
__global__ __launch_bounds__(256) void k_invy() {
    __shared__ float2 Ys[M0 * M1];
    __shared__ float2 tws[256];
    int tid = threadIdx.x;
    tws[tid] = g_tw[tid];
    int bo = blockIdx.x;
    int b = bo >> 6, o = bo & 63;
    for (int idx = tid; idx < M0 * M1; idx += 256)
        Ys[idx] = g_Yf[((size_t)b * 400 + idx) * Cn + o];
    __syncthreads();
    int y = tid;
    float2 twy[M0];
#pragma unroll
    for (int ky = 0; ky < M0; ky++) twy[ky] = tws[(ky * y) & 255];
    float2* dst = g_T2 + ((size_t)bo * Hn + y) * M1;
#pragma unroll 4
    for (int kx = 0; kx < M1; kx++) {
        float re = 0.f, im = 0.f;
#pragma unroll
        for (int ky = 0; ky < M0; ky++) {
            float2 v = Ys[ky * M1 + kx];
            float2 w = twy[ky];
            re = fmaf(v.x, w.x, fmaf(-v.y, w.y, re));
            im = fmaf(v.x, w.y, fmaf(v.y, w.x, im));
        }
        float f = (kx == 0) ? 1.f : 2.f;
        dst[kx] = make_float2(re * f, im * f);
    }
}

// ---------------- Kernel 5: inverse x-DFT + bypass + GELU (packed f32x2, conflict-free) ----------------
__device__ __forceinline__ float gelu_tanh(float v) {
    float inner = 0.7978845608028654f * v * (1.0f + 0.044715f * v * v);
    float t;
    asm("tanh.approx.f32 %0, %1;" : "=f"(t) : "f"(inner));
    return 0.5f * v * (1.0f + t);
}

__global__ __launch_bounds__(256, 2) void k_final(const float* __restrict__ x,
                                                  const float* __restrict__ conv_w,
                                                  const float* __restrict__ conv_b,
                                                  float* __restrict__ out) {
    extern __shared__ float sm[];
    float*  Xs  = sm;                                   // [64][256]
    float*  Ws  = sm + 64 * 256;                        // [i][72]
    float2* T2s = (float2*)(sm + 64 * 256 + 64 * 72);   // [o][20]
    float2* tws = T2s + 64 * 20;                        // [256]
    __shared__ float biasS[64];

    int tid = threadIdx.x;
    int b = blockIdx.x >> 8, y = blockIdx.x & 255;

    {
        const float4* xg4 = (const float4*)x;
        float4* Xs4 = (float4*)Xs;
#pragma unroll
        for (int e = 0; e < 16; e++) {
            int idx = tid + 256 * e;
            int i = idx >> 6, c4 = idx & 63;
            Xs4[idx] = xg4[((size_t)(b * 64 + i) * 256 + y) * 64 + c4];
        }
    }
    for (int idx = tid; idx < 4096; idx += 256) {
        int o = idx >> 6, i = idx & 63;
        Ws[i * 72 + o] = conv_w[idx];
    }
    for (int idx = tid; idx < 1280; idx += 256) {
        int o = idx / 20, kxx = idx - o * 20;
        T2s[idx] = g_T2[((size_t)(b * 64 + o) * Hn + y) * M1 + kxx];
    }
    tws[tid] = g_tw[tid];
    if (tid < 64) biasS[tid] = conv_b[tid];
    __syncthreads();

    int tx = tid & 31, ty = tid >> 5;
    int o0 = ty << 3;
    // thread owns x-column pairs: (2*tx + 64*p, +1), p = 0..3 (lane-contiguous LDS.64)

    ull acc[8][4];
#pragma unroll
    for (int oo = 0; oo < 8; oo++) {
        ull bv = bc2(biasS[o0 + oo]);
#pragma unroll
        for (int p = 0; p < 4; p++) acc[oo][p] = bv;
    }

    // bypass: 1x1 conv, FFMA2 over pair-strided x-pairs (conflict-free)
#pragma unroll 4
    for (int i = 0; i < 64; i++) {
        const ull* Xp = (const ull*)(Xs + i * 256);
        ull xp0 = Xp[tx];
        ull xp1 = Xp[tx + 32];
        ull xp2 = Xp[tx + 64];
        ull xp3 = Xp[tx + 96];
        float4 wa = *(const float4*)(Ws + i * 72 + o0);
        float4 wb = *(const float4*)(Ws + i * 72 + o0 + 4);
        float wv[8] = {wa.x, wa.y, wa.z, wa.w, wb.x, wb.y, wb.z, wb.w};
#pragma unroll
        for (int oo = 0; oo < 8; oo++) {
            ull wp = bc2(wv[oo]);
            acc[oo][0] = ffma2(xp0, wp, acc[oo][0]);
            acc[oo][1] = ffma2(xp1, wp, acc[oo][1]);
            acc[oo][2] = ffma2(xp2, wp, acc[oo][2]);
            acc[oo][3] = ffma2(xp3, wp, acc[oo][3]);
        }
    }

    // spectral: packed rotation recurrence over x-pairs
    ull rot_re[4], rot_im[4], rtr_re[4], rtr_im[4];
#pragma unroll
    for (int p = 0; p < 4; p++) {
        rot_re[p] = bc2(1.f);
        rot_im[p] = 0ull;
        float2 t0 = tws[2 * tx + 64 * p];
        float2 t1 = tws[2 * tx + 64 * p + 1];
        rtr_re[p] = pk2(t0.x, t1.x);
        rtr_im[p] = pk2(t0.y, t1.y);
    }
#pragma unroll 4
    for (int kx = 0; kx < 20; kx++) {
#pragma unroll
        for (int oo = 0; oo < 8; oo++) {
            float2 tv = T2s[(o0 + oo) * 20 + kx];
            ull tvx = bc2(tv.x);
            ull ntvy = bc2(-tv.y);
#pragma unroll
            for (int p = 0; p < 4; p++) {
                acc[oo][p] = ffma2(rot_re[p], tvx, acc[oo][p]);
                acc[oo][p] = ffma2(rot_im[p], ntvy, acc[oo][p]);
            }
        }
#pragma unroll
        for (int p = 0; p < 4; p++) {
            ull t1 = fmul2(rot_re[p], rtr_re[p]);
            ull nrtr = fmul2(rot_im[p], rtr_im[p]);
            ull nre = ffma2(nrtr, bc2(-1.f), t1);
            ull t2 = fmul2(rot_re[p], rtr_im[p]);
            ull nim = ffma2(rot_im[p], rtr_re[p], t2);
            rot_re[p] = nre;
            rot_im[p] = nim;
        }
    }

#pragma unroll
    for (int oo = 0; oo < 8; oo++) {
        size_t ob = (((size_t)(b * 64 + o0 + oo)) * 256 + y) * 256;
#pragma unroll
        for (int p = 0; p < 4; p++) {
            float lo, hi;
            upk2(acc[oo][p], lo, hi);
            float2 s = make_float2(gelu_tanh(lo), gelu_tanh(hi));
            *(float2*)(out + ob + 2 * tx + 64 * p) = s;
        }
    }
}

extern "C" void kernel_launch(void* const* d_in, const int* in_sizes, int n_in,
                              void* d_out, int out_size) {
    const float* x  = (const float*)d_in[0];
    const float* wr = (const float*)d_in[1];
    const float* wi = (const float*)d_in[2];
    const float* cw = (const float*)d_in[3];
    const float* cb = (const float*)d_in[4];
    float* out = (float*)d_out;

    size_t smemFinal = (size_t)(64 * 256 + 64 * 72) * sizeof(float) +
                       (size_t)(64 * 20 + 256) * sizeof(float2);   // 96256 B
    cudaFuncSetAttribute(k_final, cudaFuncAttributeMaxDynamicSharedMemorySize, (int)smemFinal);

    size_t smemFwdy = (size_t)4 * T1PITCH * sizeof(float2) + 512 * sizeof(ull);  // 168576 B
    cudaFuncSetAttribute(k_fwdy, cudaFuncAttributeMaxDynamicSharedMemorySize, (int)smemFwdy);

    k_init<<<1, 256>>>();
    k_wt<<<64 * 8, 256>>>(wr, wi);
    k_fwdx<<<Bn * Cn * Hn / 256, 256>>>(x);
    k_fwdy<<<Bn * Cn / 4, 256, smemFwdy>>>();
    k_mix<<<M0 * M1, 512>>>();
    k_invy<<<Bn * Cn, 256>>>();
    k_final<<<Bn * Hn, 256, smemFinal>>>(x, cw, cb, out);
}

// round 17
// speedup vs baseline: 1.0006x; 1.0006x over previous
#include <cuda_runtime.h>
#include <math.h>

#define Bn 16
#define Cn 64
#define Hn 256
#define Wn 256
#define M0 20
#define M1 20

typedef unsigned long long ull;

// ---- packed f32x2 helpers (Blackwell FFMA2 path, PTX-only) ----
__device__ __forceinline__ ull pk2(float lo, float hi) {
    ull r; asm("mov.b64 %0, {%1,%2};" : "=l"(r) : "f"(lo), "f"(hi)); return r;
}
__device__ __forceinline__ ull bc2(float v) {
    ull r; asm("mov.b64 %0, {%1,%1};" : "=l"(r) : "f"(v)); return r;
}
__device__ __forceinline__ ull ffma2(ull a, ull b, ull c) {
    ull d; asm("fma.rn.f32x2 %0, %1, %2, %3;" : "=l"(d) : "l"(a), "l"(b), "l"(c)); return d;
}
__device__ __forceinline__ ull fmul2(ull a, ull b) {
    ull d; asm("mul.rn.f32x2 %0, %1, %2;" : "=l"(d) : "l"(a), "l"(b)); return d;
}
__device__ __forceinline__ void upk2(ull v, float& lo, float& hi) {
    asm("mov.b64 {%0,%1}, %2;" : "=f"(lo), "=f"(hi) : "l"(v));
}

// Scratch (device globals; allocation-free per harness rules)
__device__ float2 g_tw[256];                 // e^{+2*pi*i*m/256}
__device__ float2 g_T1[Bn*Cn*M1*Hn];         // [b*64+i][kx][y]
__device__ float2 g_Xf[Bn*M0*M1*Cn];         // [b][ky][kx][i]
__device__ float2 g_Yf[Bn*M0*M1*Cn];         // [b][ky][kx][o]
__device__ float2 g_T2[Bn*Cn*Hn*M1];         // [b*64+o][y][kx]
__device__ float2 g_Wt[M0*M1*Cn*Cn];         // [mode][i*64+o]  pre-transposed weights

__global__ void k_init() {
    int m = threadIdx.x;
    double s, c;
    sincospi((double)m / 128.0, &s, &c);
    g_tw[m] = make_float2((float)c, (float)s);
}

// ---------------- weight transpose for k_mix ----------------
__global__ __launch_bounds__(256) void k_wt(const float* __restrict__ wr, const float* __restrict__ wi) {
    __shared__ float2 ts[64][51];
    int tid = threadIdx.x;
    int io0 = (blockIdx.x & 63) * 64;
    int m0  = (blockIdx.x >> 6) * 50;
    for (int idx = tid; idx < 64 * 50; idx += 256) {
        int r = idx / 50, c = idx - r * 50;
        int g = (io0 + r) * 400 + (m0 + c);
        ts[r][c] = make_float2(wr[g], wi[g]);
    }
    __syncthreads();
    for (int idx = tid; idx < 64 * 50; idx += 256) {
        int mc = idx >> 6, rc = idx & 63;
        g_Wt[(size_t)(m0 + mc) * 4096 + io0 + rc] = ts[rc][mc];
    }
}

// ---------------- Kernel 1: forward DFT along x (FFMA2, conflict-free) ----------------
__global__ __launch_bounds__(256) void k_fwdx(const float* __restrict__ x) {
    __shared__ float As[32][258];
    __shared__ float Bs[32][40];
    __shared__ float2 tws[256];
    int tid = threadIdx.x;
    tws[tid] = g_tw[tid];
    int rowBase = blockIdx.x * 256;
    int rowg = tid & 31, colg = tid >> 5;

    ull acc[4][5];
#pragma unroll
    for (int r = 0; r < 4; r++)
#pragma unroll
        for (int j = 0; j < 5; j++) acc[r][j] = 0ull;

    for (int kc = 0; kc < 256; kc += 32) {
        __syncthreads();
#pragma unroll
        for (int e = 0; e < 32; e++) {
            int idx = tid + 256 * e;
            int kloc = idx & 31;
            int r = idx >> 5;
            As[kloc][r] = x[(size_t)(rowBase + r) * 256 + kc + kloc];
        }
#pragma unroll
        for (int e = 0; e < 5; e++) {
            int idx = tid + 256 * e;
            int kloc = idx / 40;
            int j = idx - kloc * 40;
            int kx = j >> 1;
            float2 t = tws[(kx * (kc + kloc)) & 255];
            Bs[kloc][j] = (j & 1) ? -t.y : t.x;
        }
        __syncthreads();
#pragma unroll
        for (int k = 0; k < 32; k++) {
            const ull* Abase = (const ull*)(&As[k][0]);
            ull a0 = Abase[rowg];
            ull a1 = Abase[rowg + 32];
            ull a2 = Abase[rowg + 64];
            ull a3 = Abase[rowg + 96];
            ull bv[5];
#pragma unroll
            for (int j = 0; j < 5; j++) bv[j] = bc2(Bs[k][colg * 5 + j]);
#pragma unroll
            for (int j = 0; j < 5; j++) {
                acc[0][j] = ffma2(a0, bv[j], acc[0][j]);
                acc[1][j] = ffma2(a1, bv[j], acc[1][j]);
                acc[2][j] = ffma2(a2, bv[j], acc[2][j]);
                acc[3][j] = ffma2(a3, bv[j], acc[3][j]);
            }
        }
    }
    float* T1f = (float*)g_T1;
#pragma unroll
    for (int rp = 0; rp < 4; rp++) {
#pragma unroll
        for (int j = 0; j < 5; j++) {
            float lo, hi;
            upk2(acc[rp][j], lo, hi);
            int jj = colg * 5 + j;
            int kx = jj >> 1, part = jj & 1;
            int row0 = rowBase + 2 * rowg + 64 * rp;
            int bi0 = row0 >> 8, y0 = row0 & 255;
            int row1 = row0 + 1;
            int bi1 = row1 >> 8, y1 = row1 & 255;
            T1f[(((size_t)bi0 * M1 + kx) * Hn + y0) * 2 + part] = lo;
            T1f[(((size_t)bi1 * M1 + kx) * Hn + y1) * 2 + part] = hi;
        }
    }
}

// ---------------- Kernel 2: forward DFT along y (4 channels/block, packed re/im) ----------------
// thread t<200: (ky pair, kx); 4 i-channels; acc = (re,im) via (vx,vy)(c,c) + (vy,-vx)(s,s)
#define T1PITCH 5140   // 20 * 257
__global__ __launch_bounds__(256) void k_fwdy() {
    extern __shared__ char dsm[];
    float2* T1s = (float2*)dsm;                    // [4][20][257]
    ull* twc = (ull*)(dsm + 4 * T1PITCH * 8);      // (c,c) x256
    ull* twn = twc + 256;                          // (s,s) x256
    int tid = threadIdx.x;
    {
        float2 t = g_tw[tid];
        twc[tid] = bc2(t.x);
        twn[tid] = bc2(t.y);
    }
    int bi0 = blockIdx.x * 4;
    const float2* src = g_T1 + (size_t)bi0 * (M1 * Hn);
    for (int idx = tid; idx < 4 * M1 * Hn; idx += 256) {
        int iloc = idx / 5120;
        int rem = idx - iloc * 5120;
        int kx = rem >> 8, y = rem & 255;
        T1s[iloc * T1PITCH + kx * 257 + y] = src[idx];
    }
    __syncthreads();

    if (tid < 200) {
        int kyp = tid / 20, kx = tid - kyp * 20;
        int ky0 = 2 * kyp;
        ull a[4][2];
#pragma unroll
        for (int i = 0; i < 4; i++) { a[i][0] = 0ull; a[i][1] = 0ull; }
        const ull* v0 = (const ull*)(T1s + 0 * T1PITCH + kx * 257);
        const ull* v1 = (const ull*)(T1s + 1 * T1PITCH + kx * 257);
        const ull* v2 = (const ull*)(T1s + 2 * T1PITCH + kx * 257);
        const ull* v3 = (const ull*)(T1s + 3 * T1PITCH + kx * 257);
#pragma unroll 4
        for (int y = 0; y < Hn; y++) {
            int i0 = (ky0 * y) & 255;
            int i1 = ((ky0 + 1) * y) & 255;
            ull c0 = twc[i0], n0 = twn[i0];
            ull c1 = twc[i1], n1 = twn[i1];
            ull v[4] = {v0[y], v1[y], v2[y], v3[y]};
#pragma unroll
            for (int i = 0; i < 4; i++) {
                float vx, vy;
                upk2(v[i], vx, vy);
                ull vs = pk2(vy, -vx);
                a[i][0] = ffma2(v[i], c0, a[i][0]);
                a[i][0] = ffma2(vs, n0, a[i][0]);
                a[i][1] = ffma2(v[i], c1, a[i][1]);
                a[i][1] = ffma2(vs, n1, a[i][1]);
            }
        }
        int b = bi0 >> 6, ib = bi0 & 63;
#pragma unroll
        for (int i = 0; i < 4; i++) {
#pragma unroll
            for (int j = 0; j < 2; j++) {
                float re, im;
                upk2(a[i][j], re, im);
                g_Xf[((size_t)(b * M0 + ky0 + j) * M1 + kx) * Cn + ib + i] = make_float2(re, im);
            }
        }
    }
}

// ---------------- Kernel 3: mixing (512 threads, packed complex FFMA2) ----------------
__global__ __launch_bounds__(512) void k_mix() {
    __shared__ ull Ws[Cn * Cn];      // (wr,wi)
    __shared__ ull Wsw[Cn * Cn];     // (wi,wr)
    __shared__ ull Xa[Bn * Cn];      // (xr,xr)
    __shared__ ull Xb[Bn * Cn];      // (-xi,xi)
    int tid = threadIdx.x;
    int mode = blockIdx.x;
    const float2* wsrc = g_Wt + (size_t)mode * 4096;
    for (int idx = tid; idx < Cn * Cn; idx += 512) {
        float2 w = wsrc[idx];
        Ws[idx]  = pk2(w.x, w.y);
        Wsw[idx] = pk2(w.y, w.x);
    }
    for (int idx = tid; idx < Bn * Cn; idx += 512) {
        int b = idx >> 6, i = idx & 63;
        float2 xv = g_Xf[((size_t)b * 400 + mode) * Cn + i];
        Xa[idx] = bc2(xv.x);
        Xb[idx] = pk2(-xv.y, xv.y);
    }
    __syncthreads();
    const float SC = 1.0f / 65536.0f;
    int o = tid & 63, bh = tid >> 6;          // bh 0..7 -> b = bh, bh+8
    ull r0 = 0ull, r1 = 0ull;
#pragma unroll 8
    for (int i = 0; i < Cn; i++) {
        ull w = Ws[i * 64 + o];
        ull wsw = Wsw[i * 64 + o];
        r0 = ffma2(Xa[bh * 64 + i], w, r0);
        r0 = ffma2(Xb[bh * 64 + i], wsw, r0);
        r1 = ffma2(Xa[(bh + 8) * 64 + i], w, r1);
        r1 = ffma2(Xb[(bh + 8) * 64 + i], wsw, r1);
    }
    float re, im;
    upk2(r0, re, im);
    g_Yf[((size_t)bh * 400 + mode) * Cn + o] = make_float2(re * SC, im * SC);
    upk2(r1, re, im);
    g_Yf[((size_t)(bh + 8) * 400 + mode) * Cn + o] = make_float2(re * SC, im * SC);
}

// ---------------- Kernel 4: inverse DFT along y ----------------
__global__ __launch_bounds__(256) void k_invy() {
    __shared__ float2 Ys[M0 * M1];
    __shared__ float2 tws[256];
    int tid = threadIdx.x;
    tws[tid] = g_tw[tid];
    int bo = blockIdx.x;
    int b = bo >> 6, o = bo & 63;
    for (int idx = tid; idx < M0 * M1; idx += 256)
        Ys[idx] = g_Yf[((size_t)b * 400 + idx) * Cn + o];
    __syncthreads();
    int y = tid;
    float2 twy[M0];
#pragma unroll
    for (int ky = 0; ky < M0; ky++) twy[ky] = tws[(ky * y) & 255];
    float2* dst = g_T2 + ((size_t)bo * Hn + y) * M1;
#pragma unroll 4
    for (int kx = 0; kx < M1; kx++) {
        float re = 0.f, im = 0.f;
#pragma unroll
        for (int ky = 0; ky < M0; ky++) {
            float2 v = Ys[ky * M1 + kx];
            float2 w = twy[ky];
            re = fmaf(v.x, w.x, fmaf(-v.y, w.y, re));
            im = fmaf(v.x, w.y, fmaf(v.y, w.x, im));
        }
        float f = (kx == 0) ? 1.f : 2.f;
        dst[kx] = make_float2(re * f, im * f);
    }
}

// ---------------- Kernel 5: inverse x-DFT + bypass + GELU (packed f32x2, conflict-free) ----------------
__device__ __forceinline__ float gelu_tanh(float v) {
    float inner = 0.7978845608028654f * v * (1.0f + 0.044715f * v * v);
    float t;
    asm("tanh.approx.f32 %0, %1;" : "=f"(t) : "f"(inner));
    return 0.5f * v * (1.0f + t);
}

__global__ __launch_bounds__(256, 2) void k_final(const float* __restrict__ x,
                                                  const float* __restrict__ conv_w,
                                                  const float* __restrict__ conv_b,
                                                  float* __restrict__ out) {
    extern __shared__ float sm[];
    float*  Xs  = sm;                                   // [64][256]
    float*  Ws  = sm + 64 * 256;                        // [i][72]
    float2* T2s = (float2*)(sm + 64 * 256 + 64 * 72);   // [o][20]
    float2* tws = T2s + 64 * 20;                        // [256]
    __shared__ float biasS[64];

    int tid = threadIdx.x;
    int b = blockIdx.x >> 8, y = blockIdx.x & 255;

    {
        const float4* xg4 = (const float4*)x;
        float4* Xs4 = (float4*)Xs;
#pragma unroll
        for (int e = 0; e < 16; e++) {
            int idx = tid + 256 * e;
            int i = idx >> 6, c4 = idx & 63;
            Xs4[idx] = xg4[((size_t)(b * 64 + i) * 256 + y) * 64 + c4];
        }
    }
    for (int idx = tid; idx < 4096; idx += 256) {
        int o = idx >> 6, i = idx & 63;
        Ws[i * 72 + o] = conv_w[idx];
    }
    for (int idx = tid; idx < 1280; idx += 256) {
        int o = idx / 20, kxx = idx - o * 20;
        T2s[idx] = g_T2[((size_t)(b * 64 + o) * Hn + y) * M1 + kxx];
    }
    tws[tid] = g_tw[tid];
    if (tid < 64) biasS[tid] = conv_b[tid];
    __syncthreads();

    int tx = tid & 31, ty = tid >> 5;
    int o0 = ty << 3;
    // thread owns x-column pairs: (2*tx + 64*p, +1), p = 0..3 (lane-contiguous LDS.64)

    ull acc[8][4];
#pragma unroll
    for (int oo = 0; oo < 8; oo++) {
        ull bv = bc2(biasS[o0 + oo]);
#pragma unroll
        for (int p = 0; p < 4; p++) acc[oo][p] = bv;
    }

    // bypass: 1x1 conv, FFMA2 over pair-strided x-pairs (conflict-free)
#pragma unroll 4
    for (int i = 0; i < 64; i++) {
        const ull* Xp = (const ull*)(Xs + i * 256);
        ull xp0 = Xp[tx];
        ull xp1 = Xp[tx + 32];
        ull xp2 = Xp[tx + 64];
        ull xp3 = Xp[tx + 96];
        float4 wa = *(const float4*)(Ws + i * 72 + o0);
        float4 wb = *(const float4*)(Ws + i * 72 + o0 + 4);
        float wv[8] = {wa.x, wa.y, wa.z, wa.w, wb.x, wb.y, wb.z, wb.w};
#pragma unroll
        for (int oo = 0; oo < 8; oo++) {
            ull wp = bc2(wv[oo]);
            acc[oo][0] = ffma2(xp0, wp, acc[oo][0]);
            acc[oo][1] = ffma2(xp1, wp, acc[oo][1]);
            acc[oo][2] = ffma2(xp2, wp, acc[oo][2]);
            acc[oo][3] = ffma2(xp3, wp, acc[oo][3]);
        }
    }

    // spectral: packed rotation recurrence over x-pairs
    ull rot_re[4], rot_im[4], rtr_re[4], rtr_im[4];
#pragma unroll
    for (int p = 0; p < 4; p++) {
        rot_re[p] = bc2(1.f);
        rot_im[p] = 0ull;
        float2 t0 = tws[2 * tx + 64 * p];
        float2 t1 = tws[2 * tx + 64 * p + 1];
        rtr_re[p] = pk2(t0.x, t1.x);
        rtr_im[p] = pk2(t0.y, t1.y);
    }
#pragma unroll 4
    for (int kx = 0; kx < 20; kx++) {
#pragma unroll
        for (int oo = 0; oo < 8; oo++) {
            float2 tv = T2s[(o0 + oo) * 20 + kx];
            ull tvx = bc2(tv.x);
            ull ntvy = bc2(-tv.y);
#pragma unroll
            for (int p = 0; p < 4; p++) {
                acc[oo][p] = ffma2(rot_re[p], tvx, acc[oo][p]);
                acc[oo][p] = ffma2(rot_im[p], ntvy, acc[oo][p]);
            }
        }
#pragma unroll
        for (int p = 0; p < 4; p++) {
            ull t1 = fmul2(rot_re[p], rtr_re[p]);
            ull nrtr = fmul2(rot_im[p], rtr_im[p]);
            ull nre = ffma2(nrtr, bc2(-1.f), t1);
            ull t2 = fmul2(rot_re[p], rtr_im[p]);
            ull nim = ffma2(rot_im[p], rtr_re[p], t2);
            rot_re[p] = nre;
            rot_im[p] = nim;
        }
    }

#pragma unroll
    for (int oo = 0; oo < 8; oo++) {
        size_t ob = (((size_t)(b * 64 + o0 + oo)) * 256 + y) * 256;
#pragma unroll
        for (int p = 0; p < 4; p++) {
            float lo, hi;
            upk2(acc[oo][p], lo, hi);
            float2 s = make_float2(gelu_tanh(lo), gelu_tanh(hi));
            *(float2*)(out + ob + 2 * tx + 64 * p) = s;
        }
    }
}

extern "C" void kernel_launch(void* const* d_in, const int* in_sizes, int n_in,
                              void* d_out, int out_size) {
    const float* x  = (const float*)d_in[0];
    const float* wr = (const float*)d_in[1];
    const float* wi = (const float*)d_in[2];
    const float* cw = (const float*)d_in[3];
    const float* cb = (const float*)d_in[4];
    float* out = (float*)d_out;

    size_t smemFinal = (size_t)(64 * 256 + 64 * 72) * sizeof(float) +
                       (size_t)(64 * 20 + 256) * sizeof(float2);   // 96256 B
    cudaFuncSetAttribute(k_final, cudaFuncAttributeMaxDynamicSharedMemorySize, (int)smemFinal);

    size_t smemFwdy = (size_t)4 * T1PITCH * sizeof(float2) + 512 * sizeof(ull);  // 168576 B
    cudaFuncSetAttribute(k_fwdy, cudaFuncAttributeMaxDynamicSharedMemorySize, (int)smemFwdy);

    k_init<<<1, 256>>>();
    k_wt<<<64 * 8, 256>>>(wr, wi);
    k_fwdx<<<Bn * Cn * Hn / 256, 256>>>(x);
    k_fwdy<<<Bn * Cn / 4, 256, smemFwdy>>>();
    k_mix<<<M0 * M1, 512>>>();
    k_invy<<<Bn * Cn, 256>>>();
    k_final<<<Bn * Hn, 256, smemFinal>>>(x, cw, cb, out);
}